// round 11
// baseline (speedup 1.0000x reference)
#include <cuda_runtime.h>
#include <stdint.h>

// Problem constants (fixed by the reference).
#define MM      512      // checks
#define NN      1024     // variables
#define EE      3072     // edges
#define NITERS  10
#define THREADS 512
#define WB      4                 // batch lanes per CTA (2 independent float2 halves)
#define CSTRIDE 7                 // float2 slots per check per half (gcd(7,16)=1 -> conflict-free)
#define CSLOTS  (MM * CSTRIDE)    // 3584 float2 per half-buffer
#define LWSL    1088              // llr half-table slots; max lwslot(1023)=1086

#define LOG2E 1.4426950408889634f
#define LN2   0.6931471805599453f
#define CLIP  0.999995f
#define UCLAMP 24.0f              // upper clamp on log2-domain sum (overflow guard)

// ---------------- device-global scratch (no runtime allocation) --------------
// Iteration-varying weights, TRANSPOSED to per-check coalesced layout:
__device__ __align__(16) float4 g_wA[NITERS * MM];   // {w[e0][0],w[e0][1],w[e1][0],w[e1][1]}
__device__ __align__(16) float4 g_wB[NITERS * MM];   // edges 2,3
__device__ __align__(16) float4 g_wC[NITERS * MM];   // edges 4,5
__device__ __align__(16) float4 g_lwA[NITERS * MM];  // lw(var(e0..e3)) * log2e
__device__ __align__(8)  float2 g_lwB[NITERS * MM];  // lw(var(e4..e5)) * log2e
// Iteration-invariant topology (loaded once into registers):
__device__ __align__(16) uint4 g_idxA[MM];           // packed extrinsic slot pairs, edges 0..3
__device__ __align__(8)  uint2 g_idxB[MM];           // edges 4,5
__device__ __align__(16) uint4 g_vsl[MM];            // packed u16 llr-table slots (6 used)
__device__ uint2  g_finidx[MM];
__device__ float4 g_finw[MM];                        // {wf0*ln2, wf1*ln2, wf2*ln2, llr_final}

__device__ __forceinline__ int slot7(int e) { return (e / 6) * CSTRIDE + (e % 6); }
__device__ __forceinline__ int lwslot(int v) { return v + (v >> 4); }

// ---------------------------------- prep -------------------------------------
__global__ void prep_kernel(const float* __restrict__ w_iter,
                            const float* __restrict__ llr_iter,
                            const float* __restrict__ w_final,
                            const float* __restrict__ llr_final,
                            const int*   __restrict__ v_sum,
                            const int*   __restrict__ edge_var,
                            const int*   __restrict__ fin_idx) {
    int t = blockIdx.x * blockDim.x + threadIdx.x;
    if (t < NITERS * MM) {
        int it = t / MM, r = t % MM;
        const float* wi = w_iter + it * (EE * 2) + 12 * r;   // 2 weights per edge, 6 edges
        g_wA[t] = make_float4(wi[0], wi[1], wi[2],  wi[3]);
        g_wB[t] = make_float4(wi[4], wi[5], wi[6],  wi[7]);
        g_wC[t] = make_float4(wi[8], wi[9], wi[10], wi[11]);
        const float* li = llr_iter + it * NN;
        const int* ev = edge_var + 6 * r;
        g_lwA[t] = make_float4(li[ev[0]] * LOG2E, li[ev[1]] * LOG2E,
                               li[ev[2]] * LOG2E, li[ev[3]] * LOG2E);
        g_lwB[t] = make_float2(li[ev[4]] * LOG2E, li[ev[5]] * LOG2E);
    }
    if (t < MM) {
        int e0 = 6 * t;
        unsigned pk[6];
#pragma unroll
        for (int j = 0; j < 6; j++)
            pk[j] = (unsigned)slot7(v_sum[2 * (e0 + j)]) |
                    ((unsigned)slot7(v_sum[2 * (e0 + j) + 1]) << 16);
        g_idxA[t] = make_uint4(pk[0], pk[1], pk[2], pk[3]);
        g_idxB[t] = make_uint2(pk[4], pk[5]);
        const int* ev = edge_var + e0;
        g_vsl[t] = make_uint4(
            (unsigned)lwslot(ev[0]) | ((unsigned)lwslot(ev[1]) << 16),
            (unsigned)lwslot(ev[2]) | ((unsigned)lwslot(ev[3]) << 16),
            (unsigned)lwslot(ev[4]) | ((unsigned)lwslot(ev[5]) << 16), 0u);
        g_finidx[t] = make_uint2((unsigned)slot7(fin_idx[3 * t]) |
                                 ((unsigned)slot7(fin_idx[3 * t + 1]) << 16),
                                 (unsigned)slot7(fin_idx[3 * t + 2]));
        g_finw[t] = make_float4(w_final[3 * t] * LN2, w_final[3 * t + 1] * LN2,
                                w_final[3 * t + 2] * LN2, llr_final[t]);
    }
}

// ------------------------------- fast math -----------------------------------
__device__ __forceinline__ float ex2f_(float x) { float y; asm("ex2.approx.f32 %0, %1;" : "=f"(y) : "f"(x)); return y; }
__device__ __forceinline__ float lg2f_(float x) { float y; asm("lg2.approx.f32 %0, %1;" : "=f"(y) : "f"(x)); return y; }
__device__ __forceinline__ float rcpf_(float x) { float y; asm("rcp.approx.f32 %0, %1;" : "=f"(y) : "f"(x)); return y; }

__device__ __forceinline__ float2 f2mul(float2 a, float2 b) { return make_float2(a.x * b.x, a.y * b.y); }
__device__ __forceinline__ float2 f2add1(float2 a) { return make_float2(a.x + 1.f, a.y + 1.f); }
__device__ __forceinline__ float2 f2sub1(float2 a) { return make_float2(a.x - 1.f, a.y - 1.f); }
// msg = lg2(B + c*A) - lg2(B - c*A)   (log2-domain c2v; ln2 folded into consumer weights)
__device__ __forceinline__ float2 lgpair(float2 B, float2 A) {
    float2 o;
    o.x = lg2f_(fmaf(CLIP, A.x, B.x)) - lg2f_(fmaf(-CLIP, A.x, B.x));
    o.y = lg2f_(fmaf(CLIP, A.y, B.y)) - lg2f_(fmaf(-CLIP, A.y, B.y));
    return o;
}

// gather + v2c (exp-domain) for one lane-pair half of one check: fills E[6]
__device__ __forceinline__ void gather_half(const float2* __restrict__ M,
                                            const float2* __restrict__ Lt,
                                            int base, uint4 iA, uint2 iB, uint4 vp,
                                            float2* __restrict__ E) {
    float4 wA = g_wA[base], wB = g_wB[base], wC = g_wC[base];
    float4 lA = g_lwA[base];
    float2 lB = g_lwB[base];
    unsigned idx[6] = { iA.x, iA.y, iA.z, iA.w, iB.x, iB.y };
    unsigned vs[6] = { vp.x & 0xFFFFu, vp.x >> 16, vp.y & 0xFFFFu,
                       vp.y >> 16, vp.z & 0xFFFFu, vp.z >> 16 };
    float w0[6] = { wA.x, wA.z, wB.x, wB.z, wC.x, wC.z };
    float w1[6] = { wA.y, wA.w, wB.y, wB.w, wC.y, wC.w };
    float lw[6] = { lA.x, lA.y, lA.z, lA.w, lB.x, lB.y };
#pragma unroll
    for (int j = 0; j < 6; j++) {
        float2 A  = M[idx[j] & 0xFFFFu];
        float2 Bv = M[idx[j] >> 16];
        float2 L  = Lt[vs[j]];
        E[j].x = ex2f_(fminf(UCLAMP, fmaf(A.x, w0[j], fmaf(Bv.x, w1[j], L.x * lw[j]))));
        E[j].y = ex2f_(fminf(UCLAMP, fmaf(A.y, w0[j], fmaf(Bv.y, w1[j], L.y * lw[j]))));
    }
}

// check node: half-split extrinsic products of (E+1),(E-1); stores msg j to dst[j].
__device__ __forceinline__ void tree_store(const float2* __restrict__ E,
                                           float2* __restrict__ dst) {
    float2 ep3 = f2add1(E[3]), em3 = f2sub1(E[3]);
    float2 ep4 = f2add1(E[4]), em4 = f2sub1(E[4]);
    float2 ep5 = f2add1(E[5]), em5 = f2sub1(E[5]);
    float2 p34 = f2mul(ep3, ep4), m34 = f2mul(em3, em4);
    float2 H2p = f2mul(p34, ep5), H2m = f2mul(m34, em5);

    float2 ep0 = f2add1(E[0]), em0 = f2sub1(E[0]);
    float2 ep1 = f2add1(E[1]), em1 = f2sub1(E[1]);
    float2 ep2 = f2add1(E[2]), em2 = f2sub1(E[2]);
    float2 p01 = f2mul(ep0, ep1), m01 = f2mul(em0, em1);
    float2 H1p = f2mul(p01, ep2), H1m = f2mul(m01, em2);

    dst[0] = lgpair(f2mul(f2mul(ep1, ep2), H2p), f2mul(f2mul(em1, em2), H2m));
    dst[1] = lgpair(f2mul(f2mul(ep0, ep2), H2p), f2mul(f2mul(em0, em2), H2m));
    dst[2] = lgpair(f2mul(p01, H2p), f2mul(m01, H2m));
    dst[3] = lgpair(f2mul(f2mul(ep4, ep5), H1p), f2mul(f2mul(em4, em5), H1m));
    dst[4] = lgpair(f2mul(f2mul(ep3, ep5), H1p), f2mul(f2mul(em3, em5), H1m));
    dst[5] = lgpair(f2mul(p34, H1p), f2mul(m34, H1m));
}

// --------------------------------- main --------------------------------------
extern __shared__ float2 s_dyn2[];

__global__ void __launch_bounds__(THREADS, 3)
bp_kernel(const float* __restrict__ llr, float* __restrict__ out) {
    float2* M0 = s_dyn2;                    // half-buffer, lanes xy (28 KB)
    float2* M1 = s_dyn2 + CSLOTS;           // half-buffer, lanes zw (28 KB)
    float2* L0 = s_dyn2 + 2 * CSLOTS;       // llr lanes xy (8.5 KB)
    float2* L1 = L0 + LWSL;                 // llr lanes zw (8.5 KB)
    const int tid = threadIdx.x;
    const long b0 = (long)blockIdx.x * WB;
    const float* llr0 = llr + b0 * NN;

    // stage raw llr halves - once
#pragma unroll
    for (int k = 0; k < NN / THREADS; k++) {
        int v = tid + k * THREADS;
        L0[lwslot(v)] = make_float2(llr0[v],          llr0[NN + v]);
        L1[lwslot(v)] = make_float2(llr0[2 * NN + v], llr0[3 * NN + v]);
    }
    // zero both message buffers (iteration 0 reads zeros)
#pragma unroll
    for (int k = 0; k < 2 * CSLOTS / THREADS; k++)
        s_dyn2[tid + k * THREADS] = make_float2(0.f, 0.f);

    // iteration-invariant topology (packed; unpacked on use)
    uint4 iA = g_idxA[tid];
    uint2 iB = g_idxB[tid];
    uint4 vp = g_vsl[tid];
    __syncthreads();

    float2* dst0 = M0 + tid * CSTRIDE;
    float2* dst1 = M1 + tid * CSTRIDE;

    for (int it = 0; it < NITERS; it++) {
        const int base = it * MM + tid;
        {   // ---- half 0 (lanes xy) ----
            float2 E[6];
            gather_half(M0, L0, base, iA, iB, vp, E);
            __syncthreads();            // all M0 reads complete
            tree_store(E, dst0);        // write M0
        }
        {   // ---- half 1 (lanes zw) ---- overlaps half-0 stores
            float2 E[6];
            gather_half(M1, L1, base, iA, iB, vp, E);
            __syncthreads();            // all M1 reads complete; M0 writes visible
            tree_store(E, dst1);        // write M1
        }
    }
    __syncthreads();   // M1 writes visible for marginalization

    // final marginalization for variable v = tid (outputs are vars 0..511)
    uint2 fi = g_finidx[tid];
    float4 fw = g_finw[tid];
    unsigned a = fi.x & 0xFFFFu, b = fi.x >> 16, c = fi.y;
    float2 A0 = M0[a], B0 = M0[b], C0 = M0[c];
    float2 A1 = M1[a], B1 = M1[b], C1 = M1[c];
    float2 l0 = L0[lwslot(tid)], l1 = L1[lwslot(tid)];
    float ox = fmaf(A0.x, fw.x, fmaf(B0.x, fw.y, fmaf(C0.x, fw.z, l0.x * fw.w)));
    float oy = fmaf(A0.y, fw.x, fmaf(B0.y, fw.y, fmaf(C0.y, fw.z, l0.y * fw.w)));
    float oz = fmaf(A1.x, fw.x, fmaf(B1.x, fw.y, fmaf(C1.x, fw.z, l1.x * fw.w)));
    float ow = fmaf(A1.y, fw.x, fmaf(B1.y, fw.y, fmaf(C1.y, fw.z, l1.y * fw.w)));
    out[(b0 + 0) * MM + tid] = rcpf_(1.0f + ex2f_(-ox * LOG2E));
    out[(b0 + 1) * MM + tid] = rcpf_(1.0f + ex2f_(-oy * LOG2E));
    out[(b0 + 2) * MM + tid] = rcpf_(1.0f + ex2f_(-oz * LOG2E));
    out[(b0 + 3) * MM + tid] = rcpf_(1.0f + ex2f_(-ow * LOG2E));
}

// ------------------------------ launch ---------------------------------------
extern "C" void kernel_launch(void* const* d_in, const int* in_sizes, int n_in,
                              void* d_out, int out_size) {
    const float* llr       = (const float*)d_in[0];
    const float* w_iter    = (const float*)d_in[1];
    const float* llr_iter  = (const float*)d_in[2];
    const float* w_final   = (const float*)d_in[3];
    const float* llr_final = (const float*)d_in[4];
    const int*   v_sum     = (const int*)d_in[5];
    // d_in[6] = c_prod_idx: redundant (check r owns edges 6r..6r+5 contiguously)
    const int*   edge_var  = (const int*)d_in[7];
    const int*   fin_idx   = (const int*)d_in[8];

    int B = in_sizes[0] / NN;                 // 8192
    size_t smem = (size_t)(2 * CSLOTS + 2 * LWSL) * sizeof(float2);   // 73 KB

    cudaFuncSetAttribute(bp_kernel, cudaFuncAttributeMaxDynamicSharedMemorySize, (int)smem);

    prep_kernel<<<(NITERS * MM + 255) / 256, 256>>>(w_iter, llr_iter, w_final, llr_final,
                                                    v_sum, edge_var, fin_idx);
    bp_kernel<<<B / WB, THREADS, smem>>>(llr, (float*)d_out);
}

// round 13
// speedup vs baseline: 1.2760x; 1.2760x over previous
#include <cuda_runtime.h>
#include <stdint.h>

// Problem constants (fixed by the reference).
#define MM      512      // checks
#define NN      1024     // variables
#define EE      3072     // edges
#define NITERS  10
#define THREADS 512
#define WB      4                 // batch lanes per thread (float4; 2 packed f32x2 pairs)
#define CSTRIDE 7                 // float4 slots per check (112B stride -> conflict-free)
#define CSLOTS  (MM * CSTRIDE)    // 3584 float4
#define LW_SLOTS 1152             // llr table with v + (v>>3) expansion (max 1150)

#define LOG2E 1.4426950408889634f
#define LN2   0.6931471805599453f
#define CLIP  0.999995f
#define UCLAMP 24.0f              // upper clamp on log2-domain sum (overflow guard)

typedef unsigned long long u64;

// ---------------- device-global scratch (no runtime allocation) --------------
// Iteration-varying weights, TRANSPOSED to per-check coalesced layout:
__device__ __align__(16) float4 g_wA[NITERS * MM];   // {w[e0][0],w[e0][1],w[e1][0],w[e1][1]}
__device__ __align__(16) float4 g_wB[NITERS * MM];   // edges 2,3
__device__ __align__(16) float4 g_wC[NITERS * MM];   // edges 4,5
__device__ __align__(16) float4 g_lwA[NITERS * MM];  // lw(var(e0..e3)) * log2e
__device__ __align__(8)  float2 g_lwB[NITERS * MM];  // lw(var(e4..e5)) * log2e
// Iteration-invariant topology (loaded once into registers):
__device__ __align__(16) uint4 g_idxA[MM];           // packed extrinsic slot pairs, edges 0..3
__device__ __align__(8)  uint2 g_idxB[MM];           // edges 4,5
__device__ __align__(16) uint4 g_vsl[MM];            // packed u16 llr-table slots (6 used)
__device__ uint2  g_finidx[MM];
__device__ float4 g_finw[MM];                        // {wf0*ln2, wf1*ln2, wf2*ln2, llr_final}

__device__ __forceinline__ int slot7(int e) { return (e / 6) * CSTRIDE + (e % 6); }
__device__ __forceinline__ int lwslot(int v) { return v + (v >> 3); }

// ---------------------------------- prep -------------------------------------
__global__ void prep_kernel(const float* __restrict__ w_iter,
                            const float* __restrict__ llr_iter,
                            const float* __restrict__ w_final,
                            const float* __restrict__ llr_final,
                            const int*   __restrict__ v_sum,
                            const int*   __restrict__ edge_var,
                            const int*   __restrict__ fin_idx) {
    int t = blockIdx.x * blockDim.x + threadIdx.x;
    if (t < NITERS * MM) {
        int it = t / MM, r = t % MM;
        const float* wi = w_iter + it * (EE * 2) + 12 * r;   // 2 weights per edge, 6 edges
        g_wA[t] = make_float4(wi[0], wi[1], wi[2],  wi[3]);
        g_wB[t] = make_float4(wi[4], wi[5], wi[6],  wi[7]);
        g_wC[t] = make_float4(wi[8], wi[9], wi[10], wi[11]);
        const float* li = llr_iter + it * NN;
        const int* ev = edge_var + 6 * r;
        g_lwA[t] = make_float4(li[ev[0]] * LOG2E, li[ev[1]] * LOG2E,
                               li[ev[2]] * LOG2E, li[ev[3]] * LOG2E);
        g_lwB[t] = make_float2(li[ev[4]] * LOG2E, li[ev[5]] * LOG2E);
    }
    if (t < MM) {
        int e0 = 6 * t;
        unsigned pk6[6];
#pragma unroll
        for (int j = 0; j < 6; j++)
            pk6[j] = (unsigned)slot7(v_sum[2 * (e0 + j)]) |
                     ((unsigned)slot7(v_sum[2 * (e0 + j) + 1]) << 16);
        g_idxA[t] = make_uint4(pk6[0], pk6[1], pk6[2], pk6[3]);
        g_idxB[t] = make_uint2(pk6[4], pk6[5]);
        const int* ev = edge_var + e0;
        g_vsl[t] = make_uint4(
            (unsigned)lwslot(ev[0]) | ((unsigned)lwslot(ev[1]) << 16),
            (unsigned)lwslot(ev[2]) | ((unsigned)lwslot(ev[3]) << 16),
            (unsigned)lwslot(ev[4]) | ((unsigned)lwslot(ev[5]) << 16), 0u);
        g_finidx[t] = make_uint2((unsigned)slot7(fin_idx[3 * t]) |
                                 ((unsigned)slot7(fin_idx[3 * t + 1]) << 16),
                                 (unsigned)slot7(fin_idx[3 * t + 2]));
        g_finw[t] = make_float4(w_final[3 * t] * LN2, w_final[3 * t + 1] * LN2,
                                w_final[3 * t + 2] * LN2, llr_final[t]);
    }
}

// ------------------------------- fast math -----------------------------------
__device__ __forceinline__ float ex2f_(float x) { float y; asm("ex2.approx.f32 %0, %1;" : "=f"(y) : "f"(x)); return y; }
__device__ __forceinline__ float lg2f_(float x) { float y; asm("lg2.approx.f32 %0, %1;" : "=f"(y) : "f"(x)); return y; }
__device__ __forceinline__ float rcpf_(float x) { float y; asm("rcp.approx.f32 %0, %1;" : "=f"(y) : "f"(x)); return y; }

// ---- packed f32x2 (Blackwell) ----
__device__ __forceinline__ u64 pk2(float lo, float hi) {
    u64 r;
    asm("mov.b64 %0, {%1, %2};" : "=l"(r)
        : "r"(__float_as_uint(lo)), "r"(__float_as_uint(hi)));
    return r;
}
__device__ __forceinline__ void upk2(u64 v, float& lo, float& hi) {
    unsigned x, y;
    asm("mov.b64 {%0, %1}, %2;" : "=r"(x), "=r"(y) : "l"(v));
    lo = __uint_as_float(x); hi = __uint_as_float(y);
}
__device__ __forceinline__ u64 fma2_(u64 a, u64 b, u64 c) {
    u64 d; asm("fma.rn.f32x2 %0, %1, %2, %3;" : "=l"(d) : "l"(a), "l"(b), "l"(c)); return d;
}
__device__ __forceinline__ u64 mul2_(u64 a, u64 b) {
    u64 d; asm("mul.rn.f32x2 %0, %1, %2;" : "=l"(d) : "l"(a), "l"(b)); return d;
}
__device__ __forceinline__ u64 add2_(u64 a, u64 b) {
    u64 d; asm("add.rn.f32x2 %0, %1, %2;" : "=l"(d) : "l"(a), "l"(b)); return d;
}

#define ONE2P   0x3F8000003F800000ULL   // {1.0f, 1.0f}
#define NONE2P  0xBF800000BF800000ULL   // {-1.0f, -1.0f}
__device__ __forceinline__ u64 clip2p()  { return pk2(CLIP, CLIP); }
__device__ __forceinline__ u64 nclip2p() { return pk2(-CLIP, -CLIP); }

// msg (2 lanes) = lg2(B + c*A) - lg2(B - c*A), computed packed until the LG2s.
__device__ __forceinline__ float2 lgmsg(u64 B, u64 A, u64 C2, u64 NC2) {
    u64 U = fma2_(C2, A, B);
    u64 V = fma2_(NC2, A, B);
    float ua, ub, va, vb;
    upk2(U, ua, ub); upk2(V, va, vb);
    return make_float2(lg2f_(ua) - lg2f_(va), lg2f_(ub) - lg2f_(vb));
}

// check node for one packed lane-pair: half-split extrinsic products of (E+1),(E-1).
// Writes message j to dst[2*j + off] (off=0: xy pair, off=1: zw pair).
__device__ __forceinline__ void tree_packed(const u64* __restrict__ E,
                                            float2* __restrict__ dst, int off) {
    const u64 C2 = clip2p(), NC2 = nclip2p();
    u64 ep3 = add2_(E[3], ONE2P), em3 = add2_(E[3], NONE2P);
    u64 ep4 = add2_(E[4], ONE2P), em4 = add2_(E[4], NONE2P);
    u64 ep5 = add2_(E[5], ONE2P), em5 = add2_(E[5], NONE2P);
    u64 p34 = mul2_(ep3, ep4), m34 = mul2_(em3, em4);
    u64 H2p = mul2_(p34, ep5), H2m = mul2_(m34, em5);

    u64 ep0 = add2_(E[0], ONE2P), em0 = add2_(E[0], NONE2P);
    u64 ep1 = add2_(E[1], ONE2P), em1 = add2_(E[1], NONE2P);
    u64 ep2 = add2_(E[2], ONE2P), em2 = add2_(E[2], NONE2P);
    u64 p01 = mul2_(ep0, ep1), m01 = mul2_(em0, em1);
    u64 H1p = mul2_(p01, ep2), H1m = mul2_(m01, em2);

    dst[0 + off]  = lgmsg(mul2_(mul2_(ep1, ep2), H2p), mul2_(mul2_(em1, em2), H2m), C2, NC2);
    dst[2 + off]  = lgmsg(mul2_(mul2_(ep0, ep2), H2p), mul2_(mul2_(em0, em2), H2m), C2, NC2);
    dst[4 + off]  = lgmsg(mul2_(p01, H2p), mul2_(m01, H2m), C2, NC2);
    dst[6 + off]  = lgmsg(mul2_(mul2_(ep4, ep5), H1p), mul2_(mul2_(em4, em5), H1m), C2, NC2);
    dst[8 + off]  = lgmsg(mul2_(mul2_(ep3, ep5), H1p), mul2_(mul2_(em3, em5), H1m), C2, NC2);
    dst[10 + off] = lgmsg(mul2_(p34, H1p), mul2_(m34, H1m), C2, NC2);
}

// --------------------------------- main --------------------------------------
extern __shared__ float4 s_dyn[];

__global__ void __launch_bounds__(THREADS, 2)
bp_kernel(const float* __restrict__ llr, float* __restrict__ out) {
    float4* s_c2v = s_dyn;                 // CSLOTS float4 (56 KB), stride-7 padded
    float4* s_llr = s_dyn + CSLOTS;        // LW_SLOTS float4 (18 KB)
    const int tid = threadIdx.x;
    const long b0 = (long)blockIdx.x * WB;
    const float* llr0 = llr + b0 * NN;

    // stage raw llr (4 batch lanes per variable) - once
#pragma unroll
    for (int k = 0; k < NN / THREADS; k++) {
        int v = tid + k * THREADS;
        float4 L;
        L.x = llr0[v];
        L.y = llr0[NN + v];
        L.z = llr0[2 * NN + v];
        L.w = llr0[3 * NN + v];
        s_llr[lwslot(v)] = L;
    }
    // zero c2v (iteration 0 reads zeros)
#pragma unroll
    for (int k = 0; k < CSLOTS / THREADS; k++)
        s_c2v[tid + k * THREADS] = make_float4(0.f, 0.f, 0.f, 0.f);

    // iteration-invariant topology into registers
    uint4 iA = g_idxA[tid];
    uint2 iB = g_idxB[tid];
    uint4 vp = g_vsl[tid];
    unsigned idx[6] = { iA.x, iA.y, iA.z, iA.w, iB.x, iB.y };
    int vsl[6] = { (int)(vp.x & 0xFFFFu), (int)(vp.x >> 16),
                   (int)(vp.y & 0xFFFFu), (int)(vp.y >> 16),
                   (int)(vp.z & 0xFFFFu), (int)(vp.z >> 16) };
    __syncthreads();

    float2* dst = (float2*)s_c2v + tid * (2 * CSTRIDE);

    for (int it = 0; it < NITERS; it++) {
        const int base = it * MM + tid;
        float4 wA = g_wA[base], wB = g_wB[base], wC = g_wC[base];
        float4 lA = g_lwA[base];
        float2 lB = g_lwB[base];
        float w0[6] = { wA.x, wA.z, wB.x, wB.z, wC.x, wC.z };
        float w1[6] = { wA.y, wA.w, wB.y, wB.w, wC.y, wC.w };
        float lw[6] = { lA.x, lA.y, lA.z, lA.w, lB.x, lB.y };

        u64 EL[6], EH[6];   // packed e^x for lanes {x,y} and {z,w}
#pragma unroll
        for (int j = 0; j < 6; j++) {
            float4 A  = s_c2v[idx[j] & 0xFFFFu];
            float4 Bv = s_c2v[idx[j] >> 16];
            float4 L  = s_llr[vsl[j]];
            u64 w0p = pk2(w0[j], w0[j]);
            u64 w1p = pk2(w1[j], w1[j]);
            u64 lwp = pk2(lw[j], lw[j]);
            u64 uL = fma2_(pk2(A.x, A.y), w0p,
                     fma2_(pk2(Bv.x, Bv.y), w1p, mul2_(pk2(L.x, L.y), lwp)));
            u64 uH = fma2_(pk2(A.z, A.w), w0p,
                     fma2_(pk2(Bv.z, Bv.w), w1p, mul2_(pk2(L.z, L.w), lwp)));
            float u0, u1, u2, u3;
            upk2(uL, u0, u1); upk2(uH, u2, u3);
            EL[j] = pk2(ex2f_(fminf(UCLAMP, u0)), ex2f_(fminf(UCLAMP, u1)));
            EH[j] = pk2(ex2f_(fminf(UCLAMP, u2)), ex2f_(fminf(UCLAMP, u3)));
        }
        __syncthreads();   // all reads of old c2v complete

        tree_packed(EL, dst, 0);   // lanes xy
        tree_packed(EH, dst, 1);   // lanes zw
        __syncthreads();   // stores visible before next iteration's gathers
    }

    // final marginalization for variable v = tid (outputs are vars 0..511)
    uint2 fi = g_finidx[tid];
    float4 fw = g_finw[tid];
    float4 A  = s_c2v[fi.x & 0xFFFFu];
    float4 Bv = s_c2v[fi.x >> 16];
    float4 C  = s_c2v[fi.y];
    float4 L  = s_llr[lwslot(tid)];
    float4 o;
    o.x = fmaf(A.x, fw.x, fmaf(Bv.x, fw.y, fmaf(C.x, fw.z, L.x * fw.w)));
    o.y = fmaf(A.y, fw.x, fmaf(Bv.y, fw.y, fmaf(C.y, fw.z, L.y * fw.w)));
    o.z = fmaf(A.z, fw.x, fmaf(Bv.z, fw.y, fmaf(C.z, fw.z, L.z * fw.w)));
    o.w = fmaf(A.w, fw.x, fmaf(Bv.w, fw.y, fmaf(C.w, fw.z, L.w * fw.w)));
    out[(b0 + 0) * MM + tid] = rcpf_(1.0f + ex2f_(-o.x * LOG2E));
    out[(b0 + 1) * MM + tid] = rcpf_(1.0f + ex2f_(-o.y * LOG2E));
    out[(b0 + 2) * MM + tid] = rcpf_(1.0f + ex2f_(-o.z * LOG2E));
    out[(b0 + 3) * MM + tid] = rcpf_(1.0f + ex2f_(-o.w * LOG2E));
}

// ------------------------------ launch ---------------------------------------
extern "C" void kernel_launch(void* const* d_in, const int* in_sizes, int n_in,
                              void* d_out, int out_size) {
    const float* llr       = (const float*)d_in[0];
    const float* w_iter    = (const float*)d_in[1];
    const float* llr_iter  = (const float*)d_in[2];
    const float* w_final   = (const float*)d_in[3];
    const float* llr_final = (const float*)d_in[4];
    const int*   v_sum     = (const int*)d_in[5];
    // d_in[6] = c_prod_idx: redundant (check r owns edges 6r..6r+5 contiguously)
    const int*   edge_var  = (const int*)d_in[7];
    const int*   fin_idx   = (const int*)d_in[8];

    int B = in_sizes[0] / NN;                 // 8192
    size_t smem = (size_t)(CSLOTS + LW_SLOTS) * sizeof(float4);   // 74 KB

    cudaFuncSetAttribute(bp_kernel, cudaFuncAttributeMaxDynamicSharedMemorySize, (int)smem);

    prep_kernel<<<(NITERS * MM + 255) / 256, 256>>>(w_iter, llr_iter, w_final, llr_final,
                                                    v_sum, edge_var, fin_idx);
    bp_kernel<<<B / WB, THREADS, smem>>>(llr, (float*)d_out);
}